// round 1
// baseline (speedup 1.0000x reference)
#include <cuda_runtime.h>

#define BATCH 2048
#define TSEQ  100
#define DVAR  51
#define HID   128
#define G4    512
#define RPB   14      // batch rows per block
#define XTS   18      // padded transposed stride (rows dim), avoids bank conflicts, keeps 8B align
#define WSZ   (256*512)
#define NBLK  147
#define NTHR  256
#define SMEM_FLOATS (128*XTS*7 + 512*XTS)   /* x + 3h + 3c + gates = 25344 */
#define SMEM_BYTES  (SMEM_FLOATS*4)

// Transposed weights: per layer [256][512]; rows [0,128) = Wih^T (zero-padded), rows [128,256) = Whh^T
__device__ float g_wt[6*WSZ];
// fW^T padded: [128][64], cols >= 51 zero
__device__ float g_fwt[128*64];

typedef unsigned long long ull;

__device__ __forceinline__ ull dup2(float x) {
    ull r; asm("mov.b64 %0, {%1, %1};" : "=l"(r) : "f"(x)); return r;
}
__device__ __forceinline__ void fma2(ull& d, ull a, ull b) {
    asm("fma.rn.f32x2 %0, %1, %2, %0;" : "+l"(d) : "l"(a), "l"(b));
}
__device__ __forceinline__ float sigf(float x) {
    return __fdividef(1.0f, 1.0f + __expf(-x));
}

// ---------------------------------------------------------------------------
// Prep: transpose all LSTM weights (and fW) into g_wt / g_fwt
// ---------------------------------------------------------------------------
__global__ void prep_kernel(
    const float* w0, const float* u0, const float* w1, const float* u1,
    const float* w2, const float* u2, const float* w3, const float* u3,
    const float* w4, const float* u4, const float* w5, const float* u5,
    const float* fW)
{
    const float* WIH[6] = {w0, w1, w2, w3, w4, w5};
    const float* WHH[6] = {u0, u1, u2, u3, u4, u5};
    const int total = 6*WSZ + 128*64;
    for (int idx = blockIdx.x*blockDim.x + threadIdx.x; idx < total;
         idx += gridDim.x*blockDim.x) {
        if (idx < 6*WSZ) {
            int layer = idx / WSZ;
            int rem   = idx - layer*WSZ;
            int k = rem >> 9;
            int j = rem & 511;
            int din = (layer == 0 || layer == 3) ? DVAR : HID;
            float v;
            if (k < 128) v = (k < din) ? WIH[layer][j*din + k] : 0.0f;
            else         v = WHH[layer][j*HID + (k - 128)];
            g_wt[idx] = v;
        } else {
            int r2 = idx - 6*WSZ;
            int u = r2 >> 6;
            int d = r2 & 63;
            g_fwt[r2] = (d < DVAR) ? fW[d*HID + u] : 0.0f;
        }
    }
}

// ---------------------------------------------------------------------------
// GEMM partial: acc[2 cols][7 row-pairs] += x[k][rows] * W^T[k][cols]
// x is transposed in SMEM: [K][XTS]. Weights streamed from L2, coalesced LDG.64.
// FFMA2 packs row-pairs; w dup is 2 MOVs per col per k (ALU pipe, under FMA).
// ---------------------------------------------------------------------------
template<int K>
__device__ __forceinline__ void gpart(const float* __restrict__ w,
                                      const float* xin,
                                      ull* acc0, ull* acc1, int j0)
{
    const float* wp = w + j0;
    float2 cur[4];
#pragma unroll
    for (int q = 0; q < 4; q++) cur[q] = *(const float2*)(wp + q*G4);

#pragma unroll 1
    for (int kg = 0; kg < K/4; kg++) {
        float2 nxt[4];
#pragma unroll
        for (int q = 0; q < 4; q++) {
            int kn = kg*4 + 4 + q;
            if (kn >= K) kn = 0;              // clamp (value unused on last iter)
            nxt[q] = *(const float2*)(wp + kn*G4);
        }
#pragma unroll
        for (int q = 0; q < 4; q++) {
            ull wa = dup2(cur[q].x);
            ull wb = dup2(cur[q].y);
            const float* xk = xin + (kg*4 + q)*XTS;
#pragma unroll
            for (int rp = 0; rp < 7; rp++) {
                ull xp = *(const ull*)(xk + 2*rp);   // broadcast LDS.64 (row pair)
                fma2(acc0[rp], xp, wa);
                fma2(acc1[rp], xp, wb);
            }
        }
#pragma unroll
        for (int q = 0; q < 4; q++) cur[q] = nxt[q];
    }
}

// ---------------------------------------------------------------------------
// One LSTM cell for the block's RPB rows.
//   wt  : layer weight base in g_wt  ([256][512], rows 0..127 Wih^T, 128.. Whh^T)
//   xin : transposed input activations [K][XTS] (smem)
//   h,c : transposed state [128][XTS] (smem); h is read (recurrent) then updated
//   gt  : gates scratch, transposed [512][XTS]
// ---------------------------------------------------------------------------
template<int DPAD>
__device__ __noinline__ void cell(const float* __restrict__ wt,
                                  const float* __restrict__ bias,
                                  const float* xin, float* h, float* c,
                                  float* gt, int tid)
{
    const int j0 = tid << 1;
    ull acc0[7], acc1[7];
    {
        float2 bv = *(const float2*)(bias + j0);
        ull d0 = dup2(bv.x), d1 = dup2(bv.y);
#pragma unroll
        for (int rp = 0; rp < 7; rp++) { acc0[rp] = d0; acc1[rp] = d1; }
    }
    gpart<DPAD>(wt, xin, acc0, acc1, j0);
    gpart<HID>(wt + 128*G4, h, acc0, acc1, j0);

#pragma unroll
    for (int rp = 0; rp < 7; rp++) {
        *(ull*)(gt + (j0    )*XTS + 2*rp) = acc0[rp];
        *(ull*)(gt + (j0 + 1)*XTS + 2*rp) = acc1[rp];
    }
    __syncthreads();

    // elementwise LSTM update: 14*128 units over 256 threads
    {
        int u  = tid & 127;
        int rh = tid >> 7;   // 0 or 1
#pragma unroll
        for (int q = 0; q < 7; q++) {
            int r = rh*7 + q;
            float gi = gt[(u      )*XTS + r];
            float gf = gt[(u + 128)*XTS + r];
            float gg = gt[(u + 256)*XTS + r];
            float go = gt[(u + 384)*XTS + r];
            float ii = sigf(gi);
            float ff = sigf(gf);
            float oo = sigf(go);
            float tg = tanhf(gg);
            float cv = ff * c[u*XTS + r] + ii * tg;
            c[u*XTS + r] = cv;
            h[u*XTS + r] = oo * tanhf(cv);
        }
    }
    __syncthreads();
}

// ---------------------------------------------------------------------------
// Main persistent kernel: each block owns 14 batch rows, runs full enc+dec.
// ---------------------------------------------------------------------------
__global__ void __launch_bounds__(NTHR, 1) lstm_main(
    const float* __restrict__ src,
    const float* __restrict__ eb0, const float* __restrict__ eb1,
    const float* __restrict__ eb2,
    const float* __restrict__ db0, const float* __restrict__ db1,
    const float* __restrict__ db2,
    const float* __restrict__ fb,
    float* __restrict__ out)
{
    extern __shared__ float sm[];
    float* xt = sm;                        // [128][XTS]
    float* h0 = sm + 1*128*XTS;
    float* h1 = sm + 2*128*XTS;
    float* h2 = sm + 3*128*XTS;
    float* c0 = sm + 4*128*XTS;
    float* c1 = sm + 5*128*XTS;
    float* c2 = sm + 6*128*XTS;
    float* gt = sm + 7*128*XTS;            // [512][XTS]

    const int tid = threadIdx.x;
    const int b0  = blockIdx.x * RPB;

    // zero x, h, c
    for (int i = tid; i < 7*128*XTS; i += NTHR) sm[i] = 0.0f;
    __syncthreads();

    // ----------------- encoder -----------------
    for (int t = 0; t < TSEQ; t++) {
        for (int i = tid; i < DVAR*RPB; i += NTHR) {
            int r = i / DVAR;
            int k = i - r*DVAR;
            int b = b0 + r; if (b >= BATCH) b = BATCH - 1;
            xt[k*XTS + r] = src[(b*TSEQ + t)*DVAR + k];
        }
        __syncthreads();
        cell<64 >(g_wt + 0*WSZ, eb0, xt, h0, c0, gt, tid);
        cell<HID>(g_wt + 1*WSZ, eb1, h0, h1, c1, gt, tid);
        cell<HID>(g_wt + 2*WSZ, eb2, h1, h2, c2, gt, tid);
    }

    // ----------------- decoder -----------------
    for (int i = tid; i < 128*XTS; i += NTHR) xt[i] = 0.0f;  // x0 = zeros
    __syncthreads();

    for (int t = 0; t < TSEQ; t++) {
        cell<64 >(g_wt + 3*WSZ, db0, xt, h0, c0, gt, tid);
        cell<HID>(g_wt + 4*WSZ, db1, h0, h1, c1, gt, tid);
        cell<HID>(g_wt + 5*WSZ, db2, h1, h2, c2, gt, tid);

        // head: pred[r][d] = h2[r] . fW[d] + fb[d]; write out (reversed) + feed back
        {
            int d  = tid & 63;
            int rg = tid >> 6;                 // 0..3 row groups of 4
            float fbv = (d < DVAR) ? fb[d] : 0.0f;
            float acc[4];
#pragma unroll
            for (int q = 0; q < 4; q++) acc[q] = fbv;
#pragma unroll 4
            for (int u = 0; u < HID; u++) {
                float wv = g_fwt[(u << 6) + d];
#pragma unroll
                for (int q = 0; q < 4; q++) {
                    int r = rg*4 + q;
                    int rr = (r < RPB) ? r : (RPB - 1);
                    acc[q] += h2[u*XTS + rr] * wv;
                }
            }
#pragma unroll
            for (int q = 0; q < 4; q++) {
                int r = rg*4 + q;
                if (r < RPB && d < DVAR) {
                    xt[d*XTS + r] = acc[q];            // feedback input
                    int b = b0 + r;
                    if (b < BATCH)
                        out[(b*TSEQ + (TSEQ - 1 - t))*DVAR + d] = acc[q];
                }
            }
        }
        __syncthreads();
    }
}

// ---------------------------------------------------------------------------
// Input order: 0 src, then (eW,eU,eb)x3, (dW,dU,db)x3, fW, fb
// ---------------------------------------------------------------------------
extern "C" void kernel_launch(void* const* d_in, const int* in_sizes, int n_in,
                              void* d_out, int out_size)
{
    const float* src = (const float*)d_in[0];
    const float* eW0 = (const float*)d_in[1];
    const float* eU0 = (const float*)d_in[2];
    const float* eb0 = (const float*)d_in[3];
    const float* eW1 = (const float*)d_in[4];
    const float* eU1 = (const float*)d_in[5];
    const float* eb1 = (const float*)d_in[6];
    const float* eW2 = (const float*)d_in[7];
    const float* eU2 = (const float*)d_in[8];
    const float* eb2 = (const float*)d_in[9];
    const float* dW0 = (const float*)d_in[10];
    const float* dU0 = (const float*)d_in[11];
    const float* db0 = (const float*)d_in[12];
    const float* dW1 = (const float*)d_in[13];
    const float* dU1 = (const float*)d_in[14];
    const float* db1 = (const float*)d_in[15];
    const float* dW2 = (const float*)d_in[16];
    const float* dU2 = (const float*)d_in[17];
    const float* db2 = (const float*)d_in[18];
    const float* fW  = (const float*)d_in[19];
    const float* fb  = (const float*)d_in[20];
    float* out = (float*)d_out;

    cudaFuncSetAttribute(lstm_main, cudaFuncAttributeMaxDynamicSharedMemorySize,
                         SMEM_BYTES);

    prep_kernel<<<1024, 256>>>(eW0, eU0, eW1, eU1, eW2, eU2,
                               dW0, dU0, dW1, dU1, dW2, dU2, fW);
    lstm_main<<<NBLK, NTHR, SMEM_BYTES>>>(src, eb0, eb1, eb2,
                                          db0, db1, db2, fb, out);
}

// round 2
// speedup vs baseline: 1.0827x; 1.0827x over previous
#include <cuda_runtime.h>

#define BATCH 2048
#define TSEQ  100
#define DVAR  51
#define HID   128
#define G4    512
#define RPB   14      // batch rows per block
#define XTS   18      // padded transposed stride (rows dim)
#define WSZ   (256*512)
#define NBLK  147
#define NTHR  256
#define SMEM_FLOATS (128*XTS*7 + 512*XTS)   /* x + 3h + 3c + gates = 25344 */
#define SMEM_BYTES  (SMEM_FLOATS*4)

// Transposed weights: per layer [256][512]; rows [0,128) = Wih^T (zero-padded),
// rows [128,256) = Whh^T. Padded by 8 rows so the deep prefetch can read
// past the end unguarded.
__device__ float g_wt[6*WSZ + 8*G4];
// fW^T padded: [128][64], cols >= 51 zero
__device__ float g_fwt[128*64];

typedef unsigned long long ull;

__device__ __forceinline__ ull dup2(float x) {
    ull r; asm("mov.b64 %0, {%1, %1};" : "=l"(r) : "f"(x)); return r;
}
__device__ __forceinline__ void fma2(ull& d, ull a, ull b) {
    asm("fma.rn.f32x2 %0, %1, %2, %0;" : "+l"(d) : "l"(a), "l"(b));
}
__device__ __forceinline__ float sigf(float x) {
    return __fdividef(1.0f, 1.0f + __expf(-x));
}

// ---------------------------------------------------------------------------
// Prep: transpose all LSTM weights (and fW) into g_wt / g_fwt
// ---------------------------------------------------------------------------
__global__ void prep_kernel(
    const float* w0, const float* u0, const float* w1, const float* u1,
    const float* w2, const float* u2, const float* w3, const float* u3,
    const float* w4, const float* u4, const float* w5, const float* u5,
    const float* fW)
{
    const float* WIH[6] = {w0, w1, w2, w3, w4, w5};
    const float* WHH[6] = {u0, u1, u2, u3, u4, u5};
    const int total = 6*WSZ + 8*G4 + 128*64;
    for (int idx = blockIdx.x*blockDim.x + threadIdx.x; idx < total;
         idx += gridDim.x*blockDim.x) {
        if (idx < 6*WSZ) {
            int layer = idx / WSZ;
            int rem   = idx - layer*WSZ;
            int k = rem >> 9;
            int j = rem & 511;
            int din = (layer == 0 || layer == 3) ? DVAR : HID;
            float v;
            if (k < 128) v = (k < din) ? WIH[layer][j*din + k] : 0.0f;
            else         v = WHH[layer][j*HID + (k - 128)];
            g_wt[idx] = v;
        } else if (idx < 6*WSZ + 8*G4) {
            g_wt[idx] = 0.0f;                 // prefetch pad
        } else {
            int r2 = idx - (6*WSZ + 8*G4);
            int u = r2 >> 6;
            int d = r2 & 63;
            g_fwt[r2] = (d < DVAR) ? fW[d*HID + u] : 0.0f;
        }
    }
}

// ---------------------------------------------------------------------------
// GEMM partial: acc[2 cols][7 row-pairs] += x[k][rows] * W^T[k][cols]
// Weight stream register-pipelined 8 k's deep (covers ~250cyc L2 latency);
// x row-pairs double-buffered (covers 29cyc LDS latency).
// ---------------------------------------------------------------------------
template<int K>
__device__ __forceinline__ void gpart(const float* __restrict__ w,
                                      const float* xin,
                                      ull* acc0, ull* acc1, int j0)
{
    const float* wp = w + j0;
    float2 A[4], B[4];
#pragma unroll
    for (int q = 0; q < 4; q++) {
        A[q] = *(const float2*)(wp + q*G4);
        B[q] = *(const float2*)(wp + (4 + q)*G4);
    }
    ull xc[7];
#pragma unroll
    for (int rp = 0; rp < 7; rp++) xc[rp] = *(const ull*)(xin + 2*rp);

#pragma unroll 2
    for (int kg = 0; kg < K/4; kg++) {
        // prefetch weights 2 k-groups ahead (reads run into zero-pad at the end)
        float2 N[4];
#pragma unroll
        for (int q = 0; q < 4; q++)
            N[q] = *(const float2*)(wp + (kg*4 + 8 + q)*G4);
#pragma unroll
        for (int q = 0; q < 4; q++) {
            const int k = kg*4 + q;
            // prefetch x for k+1 (row K read is in-bounds smem, value unused
            // semantics-wise; last consumed x is k=K-1)
            ull xn[7];
            const float* xk = xin + (k + 1)*XTS;
#pragma unroll
            for (int rp = 0; rp < 7; rp++) xn[rp] = *(const ull*)(xk + 2*rp);

            ull wa = dup2(A[q].x);
            ull wb = dup2(A[q].y);
#pragma unroll
            for (int rp = 0; rp < 7; rp++) {
                fma2(acc0[rp], xc[rp], wa);
                fma2(acc1[rp], xc[rp], wb);
            }
#pragma unroll
            for (int rp = 0; rp < 7; rp++) xc[rp] = xn[rp];
        }
#pragma unroll
        for (int q = 0; q < 4; q++) { A[q] = B[q]; B[q] = N[q]; }
    }
}

// ---------------------------------------------------------------------------
// One LSTM cell for the block's RPB rows.
// ---------------------------------------------------------------------------
template<int DPAD>
__device__ __noinline__ void cell(const float* __restrict__ wt,
                                  const float* __restrict__ bias,
                                  const float* xin, float* h, float* c,
                                  float* gt, int tid)
{
    const int j0 = tid << 1;
    ull acc0[7], acc1[7];
    {
        float2 bv = *(const float2*)(bias + j0);
        ull d0 = dup2(bv.x), d1 = dup2(bv.y);
#pragma unroll
        for (int rp = 0; rp < 7; rp++) { acc0[rp] = d0; acc1[rp] = d1; }
    }
    gpart<DPAD>(wt, xin, acc0, acc1, j0);
    gpart<HID>(wt + 128*G4, h, acc0, acc1, j0);

#pragma unroll
    for (int rp = 0; rp < 7; rp++) {
        *(ull*)(gt + (j0    )*XTS + 2*rp) = acc0[rp];
        *(ull*)(gt + (j0 + 1)*XTS + 2*rp) = acc1[rp];
    }
    __syncthreads();

    // elementwise LSTM update: 14*128 units over 256 threads
    {
        int u  = tid & 127;
        int rh = tid >> 7;   // 0 or 1
#pragma unroll
        for (int q = 0; q < 7; q++) {
            int r = rh*7 + q;
            float gi = gt[(u      )*XTS + r];
            float gf = gt[(u + 128)*XTS + r];
            float gg = gt[(u + 256)*XTS + r];
            float go = gt[(u + 384)*XTS + r];
            float ii = sigf(gi);
            float ff = sigf(gf);
            float oo = sigf(go);
            float tg = tanhf(gg);
            float cv = ff * c[u*XTS + r] + ii * tg;
            c[u*XTS + r] = cv;
            h[u*XTS + r] = oo * tanhf(cv);
        }
    }
    __syncthreads();
}

// ---------------------------------------------------------------------------
// Main persistent kernel: each block owns 14 batch rows, runs full enc+dec.
// ---------------------------------------------------------------------------
__global__ void __launch_bounds__(NTHR, 1) lstm_main(
    const float* __restrict__ src,
    const float* __restrict__ eb0, const float* __restrict__ eb1,
    const float* __restrict__ eb2,
    const float* __restrict__ db0, const float* __restrict__ db1,
    const float* __restrict__ db2,
    const float* __restrict__ fb,
    float* __restrict__ out)
{
    extern __shared__ float sm[];
    float* xt = sm;                        // [128][XTS]
    float* h0 = sm + 1*128*XTS;
    float* h1 = sm + 2*128*XTS;
    float* h2 = sm + 3*128*XTS;
    float* c0 = sm + 4*128*XTS;
    float* c1 = sm + 5*128*XTS;
    float* c2 = sm + 6*128*XTS;
    float* gt = sm + 7*128*XTS;            // [512][XTS]

    const int tid = threadIdx.x;
    const int b0  = blockIdx.x * RPB;

    // zero x, h, c
    for (int i = tid; i < 7*128*XTS; i += NTHR) sm[i] = 0.0f;
    __syncthreads();

    // ----------------- encoder -----------------
    for (int t = 0; t < TSEQ; t++) {
        for (int i = tid; i < DVAR*RPB; i += NTHR) {
            int r = i / DVAR;
            int k = i - r*DVAR;
            int b = b0 + r; if (b >= BATCH) b = BATCH - 1;
            xt[k*XTS + r] = src[(b*TSEQ + t)*DVAR + k];
        }
        __syncthreads();
        cell<64 >(g_wt + 0*WSZ, eb0, xt, h0, c0, gt, tid);
        cell<HID>(g_wt + 1*WSZ, eb1, h0, h1, c1, gt, tid);
        cell<HID>(g_wt + 2*WSZ, eb2, h1, h2, c2, gt, tid);
    }

    // ----------------- decoder -----------------
    for (int i = tid; i < 128*XTS; i += NTHR) xt[i] = 0.0f;  // x0 = zeros
    __syncthreads();

    for (int t = 0; t < TSEQ; t++) {
        cell<64 >(g_wt + 3*WSZ, db0, xt, h0, c0, gt, tid);
        cell<HID>(g_wt + 4*WSZ, db1, h0, h1, c1, gt, tid);
        cell<HID>(g_wt + 5*WSZ, db2, h1, h2, c2, gt, tid);

        // head: pred[r][d] = h2[r] . fW[d] + fb[d]; write out (reversed) + feed back
        {
            int d  = tid & 63;
            int rg = tid >> 6;                 // 0..3 row groups of 4
            float fbv = (d < DVAR) ? fb[d] : 0.0f;
            float acc[4];
#pragma unroll
            for (int q = 0; q < 4; q++) acc[q] = fbv;
#pragma unroll 4
            for (int u = 0; u < HID; u++) {
                float wv = g_fwt[(u << 6) + d];
#pragma unroll
                for (int q = 0; q < 4; q++) {
                    int r = rg*4 + q;
                    int rr = (r < RPB) ? r : (RPB - 1);
                    acc[q] += h2[u*XTS + rr] * wv;
                }
            }
#pragma unroll
            for (int q = 0; q < 4; q++) {
                int r = rg*4 + q;
                if (r < RPB && d < DVAR) {
                    xt[d*XTS + r] = acc[q];            // feedback input
                    int b = b0 + r;
                    if (b < BATCH)
                        out[(b*TSEQ + (TSEQ - 1 - t))*DVAR + d] = acc[q];
                }
            }
        }
        __syncthreads();
    }
}

// ---------------------------------------------------------------------------
// Input order: 0 src, then (eW,eU,eb)x3, (dW,dU,db)x3, fW, fb
// ---------------------------------------------------------------------------
extern "C" void kernel_launch(void* const* d_in, const int* in_sizes, int n_in,
                              void* d_out, int out_size)
{
    const float* src = (const float*)d_in[0];
    const float* eW0 = (const float*)d_in[1];
    const float* eU0 = (const float*)d_in[2];
    const float* eb0 = (const float*)d_in[3];
    const float* eW1 = (const float*)d_in[4];
    const float* eU1 = (const float*)d_in[5];
    const float* eb1 = (const float*)d_in[6];
    const float* eW2 = (const float*)d_in[7];
    const float* eU2 = (const float*)d_in[8];
    const float* eb2 = (const float*)d_in[9];
    const float* dW0 = (const float*)d_in[10];
    const float* dU0 = (const float*)d_in[11];
    const float* db0 = (const float*)d_in[12];
    const float* dW1 = (const float*)d_in[13];
    const float* dU1 = (const float*)d_in[14];
    const float* db1 = (const float*)d_in[15];
    const float* dW2 = (const float*)d_in[16];
    const float* dU2 = (const float*)d_in[17];
    const float* db2 = (const float*)d_in[18];
    const float* fW  = (const float*)d_in[19];
    const float* fb  = (const float*)d_in[20];
    float* out = (float*)d_out;

    cudaFuncSetAttribute(lstm_main, cudaFuncAttributeMaxDynamicSharedMemorySize,
                         SMEM_BYTES);

    prep_kernel<<<1024, 256>>>(eW0, eU0, eW1, eU1, eW2, eU2,
                               dW0, dU0, dW1, dU1, dW2, dU2, fW);
    lstm_main<<<NBLK, NTHR, SMEM_BYTES>>>(src, eb0, eb1, eb2,
                                          db0, db1, db2, fb, out);
}